// round 1
// baseline (speedup 1.0000x reference)
#include <cuda_runtime.h>

#define CIN   256
#define COUT  256
#define HWD   64
#define NB    32
#define NPIX  (HWD * HWD)       // 4096
#define KPOS  9
#define WT_ELEMS (KPOS * CIN * COUT)   // 589824

// ---------------- scratch (device globals: no allocations allowed) ----------
__device__ float g_wt[WT_ELEMS];                     // weight^T  [kpos][ci][co]
__device__ float g_wsq[COUT * CIN];                  // sum_k w^2 [co][ci]
__device__ float g_dmod[NB * COUT];                  // demod     [b][co]
__device__ float g_wbuf[(size_t)NB * WT_ELEMS];      // modulated [b][kpos][ci][co]  (~75.5 MB)

// ---------------- packed fp32x2 helpers --------------------------------------
__device__ __forceinline__ unsigned long long pack2(float lo, float hi) {
    unsigned long long r;
    asm("mov.b64 %0, {%1, %2};" : "=l"(r)
        : "r"(__float_as_uint(lo)), "r"(__float_as_uint(hi)));
    return r;
}
__device__ __forceinline__ void unpack2(unsigned long long v, float& lo, float& hi) {
    unsigned int a, b;
    asm("mov.b64 {%0, %1}, %2;" : "=r"(a), "=r"(b) : "l"(v));
    lo = __uint_as_float(a);
    hi = __uint_as_float(b);
}
#define FMA2(d, a, b, c) \
    asm("fma.rn.f32x2 %0, %1, %2, %3;" : "=l"(d) : "l"(a), "l"(b), "l"(c))

// ---------------- prologue kernels ------------------------------------------
// weight [co][ci][kp] -> g_wt [kp][ci][co]
__global__ void k_transpose(const float* __restrict__ w) {
    int idx = blockIdx.x * blockDim.x + threadIdx.x;
    if (idx >= WT_ELEMS) return;
    int co = idx & 255;
    int ci = (idx >> 8) & 255;
    int kp = idx >> 16;
    g_wt[idx] = w[co * (CIN * KPOS) + ci * KPOS + kp];
}

// g_wsq[co*256+ci] = sum_k weight[co][ci][k]^2   (idx*9 == co*2304+ci*9)
__global__ void k_wsq(const float* __restrict__ w) {
    int idx = blockIdx.x * blockDim.x + threadIdx.x;
    if (idx >= COUT * CIN) return;
    const float* p = w + idx * KPOS;
    float s = 0.f;
#pragma unroll
    for (int k = 0; k < KPOS; k++) { float v = p[k]; s += v * v; }
    g_wsq[idx] = s;
}

// g_dmod[b][co] = rsqrt( sum_ci wsq[co][ci]*(y[b][ci]+1)^2 + 1e-8 )
__global__ void k_demod(const float* __restrict__ y) {
    int co = blockIdx.x, b = blockIdx.y, t = threadIdx.x;   // 256 threads
    float ym = y[b * CIN + t] + 1.0f;
    float v = g_wsq[co * CIN + t] * ym * ym;
#pragma unroll
    for (int o = 16; o; o >>= 1) v += __shfl_xor_sync(0xffffffffu, v, o);
    __shared__ float sr[8];
    if ((t & 31) == 0) sr[t >> 5] = v;
    __syncthreads();
    if (t == 0) {
        float s = 0.f;
#pragma unroll
        for (int i = 0; i < 8; i++) s += sr[i];
        g_dmod[b * COUT + co] = rsqrtf(s + 1e-8f);
    }
}

// g_wbuf[b][kp][ci][co] = wt[kp][ci][co] * (y[b][ci]+1) * dmod[b][co]
__global__ void k_scale(const float* __restrict__ y) {
    int idx = blockIdx.x * blockDim.x + threadIdx.x;   // exact grid, no guard needed
    int co = idx & 255;
    int ci = (idx >> 8) & 255;
    int kq = idx >> 16;          // b*9 + kp
    int b  = kq / 9;
    g_wbuf[idx] = g_wt[idx % WT_ELEMS] * (y[b * CIN + ci] + 1.0f) * g_dmod[b * COUT + co];
}

// ---------------- implicit-GEMM conv ----------------------------------------
// Per sample b:  out[m, p] = sum_{kp, ci} wbuf[b][kp][ci][m] * xshift(kp)[ci][p]
// Tile: 128(M) x 128(N) x 16(K), 256 threads, 8x8 micro-tile, f32x2 packed FMA.
__global__ void __launch_bounds__(256) k_conv(const float* __restrict__ x,
                                              const float* __restrict__ bias,
                                              float* __restrict__ out) {
    const int b  = blockIdx.z;
    const int m0 = blockIdx.y * 128;
    const int n0 = blockIdx.x * 128;

    __shared__ __align__(16) float As[16][128];
    __shared__ __align__(16) float Bs[16][128];

    const int t  = threadIdx.x;
    const int tx = t & 15;
    const int ty = t >> 4;

    const float* xb = x + (size_t)b * CIN * NPIX;
    const float* wb = g_wbuf + (size_t)b * WT_ELEMS;

    // A loader: 2 float4 per thread covering As[16][128]
    const int a_row = t >> 5;         // 0..7 (and +8)
    const int a_col = (t & 31) * 4;   // 0..124
    // B loader: 8 scalars per thread, fixed pixel column, rows b_k0 + 2*i
    const int b_n  = t & 127;
    const int b_k0 = t >> 7;          // 0 or 1
    const int p    = n0 + b_n;
    const int pr   = p >> 6;
    const int pc   = p & 63;

    unsigned long long acc[8][4];
#pragma unroll
    for (int i = 0; i < 8; i++)
#pragma unroll
        for (int j = 0; j < 4; j++) acc[i][j] = 0ull;

    // fetch tile kt into registers
    auto fetch = [&](int kt, float4& A0, float4& A1, float (&Bv)[8]) {
        const int kp = kt >> 4;             // 0..8
        const int cc = (kt & 15) * 16;      // ci chunk base
        const float* abase = wb + ((kp * CIN) + cc + a_row) * COUT + m0 + a_col;
        A0 = *(const float4*)abase;
        A1 = *(const float4*)(abase + 8 * COUT);

        const int dr = kp / 3 - 1;
        const int dc = kp % 3 - 1;
        const int r2 = pr + dr;
        const int c2 = pc + dc;
        const bool ok = ((unsigned)r2 < (unsigned)HWD) && ((unsigned)c2 < (unsigned)HWD);
        const float* xp = xb + (cc + b_k0) * NPIX + r2 * HWD + c2;
#pragma unroll
        for (int i = 0; i < 8; i++)
            Bv[i] = ok ? xp[2 * i * NPIX] : 0.f;
    };
    auto store_tile = [&](const float4& A0, const float4& A1, const float (&Bv)[8]) {
        *(float4*)&As[a_row][a_col]     = A0;
        *(float4*)&As[8 + a_row][a_col] = A1;
#pragma unroll
        for (int i = 0; i < 8; i++) Bs[b_k0 + 2 * i][b_n] = Bv[i];
    };

    const int NT = KPOS * (CIN / 16);   // 144 k-tiles
    {
        float4 A0, A1; float Bv[8];
        fetch(0, A0, A1, Bv);
        store_tile(A0, A1, Bv);
    }
    __syncthreads();

    for (int kt = 0; kt < NT; kt++) {
        float4 nA0, nA1; float nB[8];
        if (kt + 1 < NT) fetch(kt + 1, nA0, nA1, nB);

#pragma unroll
        for (int k = 0; k < 16; k++) {
            float4 a0 = *(const float4*)&As[k][ty * 8];
            float4 a1 = *(const float4*)&As[k][ty * 8 + 4];
            float4 b0 = *(const float4*)&Bs[k][tx * 8];
            float4 b1 = *(const float4*)&Bs[k][tx * 8 + 4];
            unsigned long long bp[4];
            bp[0] = pack2(b0.x, b0.y);
            bp[1] = pack2(b0.z, b0.w);
            bp[2] = pack2(b1.x, b1.y);
            bp[3] = pack2(b1.z, b1.w);
            float av[8] = {a0.x, a0.y, a0.z, a0.w, a1.x, a1.y, a1.z, a1.w};
#pragma unroll
            for (int i = 0; i < 8; i++) {
                unsigned long long pa = pack2(av[i], av[i]);
                FMA2(acc[i][0], pa, bp[0], acc[i][0]);
                FMA2(acc[i][1], pa, bp[1], acc[i][1]);
                FMA2(acc[i][2], pa, bp[2], acc[i][2]);
                FMA2(acc[i][3], pa, bp[3], acc[i][3]);
            }
        }
        __syncthreads();
        if (kt + 1 < NT) store_tile(nA0, nA1, nB);
        __syncthreads();
    }

    // epilogue: unpack, add bias, store
#pragma unroll
    for (int i = 0; i < 8; i++) {
        const int m = m0 + ty * 8 + i;
        const float bv = bias[m];
        float r[8];
#pragma unroll
        for (int j = 0; j < 4; j++) {
            float lo, hi;
            unpack2(acc[i][j], lo, hi);
            r[2 * j]     = lo + bv;
            r[2 * j + 1] = hi + bv;
        }
        float* op = out + ((size_t)(b * COUT + m)) * NPIX + n0 + tx * 8;
        *(float4*)op       = make_float4(r[0], r[1], r[2], r[3]);
        *(float4*)(op + 4) = make_float4(r[4], r[5], r[6], r[7]);
    }
}

// ---------------- launch ------------------------------------------------------
extern "C" void kernel_launch(void* const* d_in, const int* in_sizes, int n_in,
                              void* d_out, int out_size) {
    const float* x    = (const float*)d_in[0];
    const float* y    = (const float*)d_in[1];
    const float* w    = (const float*)d_in[2];
    const float* bias = (const float*)d_in[3];
    float* out        = (float*)d_out;

    k_transpose<<<(WT_ELEMS + 255) / 256, 256>>>(w);
    k_wsq<<<(COUT * CIN + 255) / 256, 256>>>(w);
    k_demod<<<dim3(COUT, NB), 256>>>(y);
    k_scale<<<(NB * WT_ELEMS) / 256, 256>>>(y);
    k_conv<<<dim3(NPIX / 128, COUT / 128, NB), 256>>>(x, bias, out);
}

// round 3
// speedup vs baseline: 1.9645x; 1.9645x over previous
#include <cuda_runtime.h>
#include <cuda_bf16.h>
#include <cstdint>

#define CIN   256
#define COUT  256
#define HWD   64
#define NB    32
#define NPIX  4096
#define KTOT  2304            // 9 * 256
#define NSTAGE 72             // K chunks of 32

#define XROW  272             // padded row bytes for x tile [k][pix]
#define WROW  80              // padded row bytes for w tile [co][k]
#define X_SZ  (32 * XROW)     // 8704 per split
#define W_SZ  (256 * WROW)    // 20480 per split
#define OXH   0
#define OXL   X_SZ
#define OWH   (2 * X_SZ)
#define OWL   (2 * X_SZ + W_SZ)
#define STAGE_SZ (2 * X_SZ + 2 * W_SZ)   // 58368
#define SMEM_BYTES (2 * STAGE_SZ)        // 116736

// ---------------- device scratch ---------------------------------------------
__device__ float g_wsq[COUT * CIN];
__device__ float g_dmod[NB * COUT];
__device__ __nv_bfloat16 g_wh[(size_t)NB * COUT * KTOT];   // modulated w hi, K-major
__device__ __nv_bfloat16 g_wl[(size_t)NB * COUT * KTOT];   // modulated w lo, K-major

// ---------------- helpers -----------------------------------------------------
__device__ __forceinline__ uint32_t smem_u32(const void* p) {
    uint32_t a;
    asm("{ .reg .u64 t; cvta.to.shared.u64 t, %1; cvt.u32.u64 %0, t; }" : "=r"(a) : "l"(p));
    return a;
}
__device__ __forceinline__ void cp16(uint32_t dst, const void* src) {
    asm volatile("cp.async.cg.shared.global [%0], [%1], 16;" :: "r"(dst), "l"(src));
}
__device__ __forceinline__ void cp_commit() { asm volatile("cp.async.commit_group;"); }
__device__ __forceinline__ void cp_wait0()  { asm volatile("cp.async.wait_group 0;"); }

__device__ __forceinline__ void ldsm4(uint32_t* r, uint32_t a) {
    asm volatile("ldmatrix.sync.aligned.m8n8.x4.shared.b16 {%0,%1,%2,%3}, [%4];"
                 : "=r"(r[0]), "=r"(r[1]), "=r"(r[2]), "=r"(r[3]) : "r"(a));
}
__device__ __forceinline__ void ldsm4t(uint32_t* r, uint32_t a) {
    asm volatile("ldmatrix.sync.aligned.m8n8.x4.trans.shared.b16 {%0,%1,%2,%3}, [%4];"
                 : "=r"(r[0]), "=r"(r[1]), "=r"(r[2]), "=r"(r[3]) : "r"(a));
}
__device__ __forceinline__ void mma16816(float* c, const uint32_t* a, const uint32_t* b) {
    asm volatile("mma.sync.aligned.m16n8k16.row.col.f32.bf16.bf16.f32 "
                 "{%0,%1,%2,%3}, {%4,%5,%6,%7}, {%8,%9}, {%0,%1,%2,%3};"
                 : "+f"(c[0]), "+f"(c[1]), "+f"(c[2]), "+f"(c[3])
                 : "r"(a[0]), "r"(a[1]), "r"(a[2]), "r"(a[3]), "r"(b[0]), "r"(b[1]));
}

// ---------------- prologue ----------------------------------------------------
__global__ void k_wsq(const float* __restrict__ w) {
    int idx = blockIdx.x * blockDim.x + threadIdx.x;   // co*256+ci
    const float* p = w + idx * 9;
    float s = 0.f;
#pragma unroll
    for (int k = 0; k < 9; k++) { float v = p[k]; s += v * v; }
    g_wsq[idx] = s;
}

__global__ void k_demod(const float* __restrict__ y) {
    int co = blockIdx.x, b = blockIdx.y, t = threadIdx.x;
    float ym = y[b * CIN + t] + 1.0f;
    float v = g_wsq[co * CIN + t] * ym * ym;
#pragma unroll
    for (int o = 16; o; o >>= 1) v += __shfl_xor_sync(0xffffffffu, v, o);
    __shared__ float sr[8];
    if ((t & 31) == 0) sr[t >> 5] = v;
    __syncthreads();
    if (t == 0) {
        float s = 0.f;
#pragma unroll
        for (int i = 0; i < 8; i++) s += sr[i];
        g_dmod[b * COUT + co] = rsqrtf(s + 1e-8f);
    }
}

// modulate + demodulate + bf16 hi/lo split; K-major [b][co][kp*256+ci]
__global__ void k_wsplit(const float* __restrict__ w, const float* __restrict__ y) {
    int t = blockIdx.x * 256 + threadIdx.x;
    int cih = t & 127;
    int r   = t >> 7;
    int kp  = r % 9;
    int bc  = r / 9;
    int co = bc & 255, b = bc >> 8;
    int ci = cih * 2;
    float d  = g_dmod[b * COUT + co];
    float y0 = y[b * CIN + ci]     + 1.f;
    float y1 = y[b * CIN + ci + 1] + 1.f;
    float v0 = w[co * KTOT + ci * 9 + kp]       * y0 * d;
    float v1 = w[co * KTOT + (ci + 1) * 9 + kp] * y1 * d;
    __nv_bfloat16 h0 = __float2bfloat16(v0), h1 = __float2bfloat16(v1);
    __nv_bfloat16 l0 = __float2bfloat16(v0 - __bfloat162float(h0));
    __nv_bfloat16 l1 = __float2bfloat16(v1 - __bfloat162float(h1));
    size_t o = ((size_t)(b * COUT + co)) * KTOT + kp * CIN + ci;
    g_wh[o] = h0; g_wh[o + 1] = h1;
    g_wl[o] = l0; g_wl[o + 1] = l1;
}

// ---------------- main conv: HMMA bf16x3 implicit GEMM ------------------------
// CTA: 128 pixels (M) x 256 cout (N), K = 2304 (kp*256+ci), double-buffered k32.
__global__ void __launch_bounds__(256, 1) k_conv(const float* __restrict__ x,
                                                 const float* __restrict__ bias,
                                                 float* __restrict__ out) {
    extern __shared__ char smem[];
    const uint32_t sb0 = smem_u32(smem);
    const int t  = threadIdx.x;
    const int l  = t & 31;
    const int w  = t >> 5;
    const int wm = w & 1;           // pixel half (64)
    const int wn = w >> 1;          // cout quarter (64)
    const int b  = blockIdx.y;
    const int n0 = blockIdx.x * 128;

    const float* xb = x + (size_t)b * CIN * NPIX;
    const __nv_bfloat16* gwh = g_wh + (size_t)b * COUT * KTOT;
    const __nv_bfloat16* gwl = g_wl + (size_t)b * COUT * KTOT;

    // per-lane ldmatrix address components
    const uint32_t a_lane = (uint32_t)(((l & 7) + ((l >> 4) & 1) * 8) * XROW
                                       + (wm * 64 + ((l >> 3) & 1) * 8) * 2);
    const uint32_t b_lane = (uint32_t)(((l & 7) + ((l >> 4) & 1) * 8) * WROW
                                       + ((l >> 3) & 1) * 16);

    // x loader geometry: j = 0..15 -> ci = (w*16+j)>>2 ... closed forms:
    const int xg = w;               // warp id
    float acc[4][8][4];
#pragma unroll
    for (int i = 0; i < 4; i++)
#pragma unroll
        for (int jn = 0; jn < 8; jn++)
#pragma unroll
            for (int kk = 0; kk < 4; kk++) acc[i][jn][kk] = 0.f;

    float xv[16];

    // ---- loaders for stage c into buffer buf ----
    auto load_x_regs = [&](int c) {
        const int kp  = c / 8;
        const int cic = (c & 7) * 32;
        const int dr = kp / 3 - 1, dc = kp % 3 - 1;
        const int rbase = (n0 >> 6) + dr;
#pragma unroll
        for (int j = 0; j < 16; j++) {
            const int ci = xg * 4 + (j >> 2);
            const int r2 = rbase + ((j >> 1) & 1);
            const int c2 = (j & 1) * 32 + l + dc;
            const bool ok = ((unsigned)r2 < HWD) && ((unsigned)c2 < HWD);
            xv[j] = ok ? __ldg(xb + (size_t)(cic + ci) * NPIX + r2 * HWD + c2) : 0.f;
        }
    };
    auto store_x = [&](int buf) {
        const uint32_t sx = sb0 + buf * STAGE_SZ;
#pragma unroll
        for (int j = 0; j < 16; j++) {
            const int ci = xg * 4 + (j >> 2);
            const int p  = (j & 3) * 32 + l;
            float v = xv[j];
            __nv_bfloat16 h = __float2bfloat16(v);
            __nv_bfloat16 lo = __float2bfloat16(v - __bfloat162float(h));
            uint32_t off = (uint32_t)(ci * XROW + p * 2);
            *(__nv_bfloat16*)(smem + (sx - sb0) + OXH + off) = h;
            *(__nv_bfloat16*)(smem + (sx - sb0) + OXL + off) = lo;
        }
    };
    auto load_w = [&](int c, int buf) {
        const int kp  = c / 8;
        const int cic = (c & 7) * 32;
        const size_t go = (size_t)t * KTOT + kp * 256 + cic;
        const uint32_t dh = sb0 + buf * STAGE_SZ + OWH + t * WROW;
        const uint32_t dl = sb0 + buf * STAGE_SZ + OWL + t * WROW;
        const __nv_bfloat16* sh = gwh + go;
        const __nv_bfloat16* sl = gwl + go;
#pragma unroll
        for (int q = 0; q < 4; q++) {
            cp16(dh + q * 16, sh + q * 8);
            cp16(dl + q * 16, sl + q * 8);
        }
    };

    // ---- prime stage 0 ----
    load_x_regs(0);
    load_w(0, 0);
    cp_commit();
    store_x(0);
    cp_wait0();
    __syncthreads();

#pragma unroll 1
    for (int c = 0; c < NSTAGE; c++) {
        const int buf = c & 1;
        const uint32_t sb = sb0 + buf * STAGE_SZ;
        const bool more = (c + 1 < NSTAGE);
        if (more) { load_x_regs(c + 1); load_w(c + 1, buf ^ 1); cp_commit(); }

        // ---- compute stage c ----
#pragma unroll
        for (int s = 0; s < 2; s++) {
            uint32_t Ah[16], Al[16];
            const uint32_t ax = sb + OXH + a_lane + s * 16 * XROW;
#pragma unroll
            for (int mt = 0; mt < 4; mt++) ldsm4t(Ah + mt * 4, ax + mt * 32);
#pragma unroll
            for (int mt = 0; mt < 4; mt++) ldsm4t(Al + mt * 4, ax + X_SZ + mt * 32);
#pragma unroll
            for (int h = 0; h < 2; h++) {
                uint32_t Bh[8], Bl[8];
                const uint32_t bw = sb + OWH + b_lane + (wn * 64 + h * 32) * WROW + s * 32;
                ldsm4(Bh,     bw);
                ldsm4(Bh + 4, bw + 16 * WROW);
                ldsm4(Bl,     bw + W_SZ);
                ldsm4(Bl + 4, bw + W_SZ + 16 * WROW);
#pragma unroll
                for (int mt = 0; mt < 4; mt++)
#pragma unroll
                    for (int q = 0; q < 4; q++) {
                        float* C = acc[mt][h * 4 + q];
                        mma16816(C, Ah + mt * 4, Bh + q * 2);
                        mma16816(C, Ah + mt * 4, Bl + q * 2);
                        mma16816(C, Al + mt * 4, Bh + q * 2);
                    }
            }
        }

        if (more) store_x(buf ^ 1);
        cp_wait0();
        __syncthreads();
    }

    // ---- epilogue ----
#pragma unroll
    for (int h = 0; h < 2; h++)
#pragma unroll
        for (int q = 0; q < 4; q++) {
            const int co0 = wn * 64 + h * 32 + (q >> 1) * 16 + (q & 1) * 8 + (l & 3) * 2;
            const float b0 = __ldg(&bias[co0]);
            const float b1 = __ldg(&bias[co0 + 1]);
#pragma unroll
            for (int mt = 0; mt < 4; mt++) {
                const int pix = n0 + wm * 64 + mt * 16 + (l >> 2);
                float* o = out + ((size_t)b * COUT + co0) * NPIX + pix;
                const float* C = acc[mt][h * 4 + q];
                o[0]        = C[0] + b0;
                o[NPIX]     = C[1] + b1;
                o[8]        = C[2] + b0;
                o[NPIX + 8] = C[3] + b1;
            }
        }
}

// ---------------- launch ------------------------------------------------------
extern "C" void kernel_launch(void* const* d_in, const int* in_sizes, int n_in,
                              void* d_out, int out_size) {
    const float* x    = (const float*)d_in[0];
    const float* y    = (const float*)d_in[1];
    const float* w    = (const float*)d_in[2];
    const float* bias = (const float*)d_in[3];
    float* out        = (float*)d_out;

    cudaFuncSetAttribute(k_conv, cudaFuncAttributeMaxDynamicSharedMemorySize, SMEM_BYTES);

    k_wsq<<<COUT * CIN / 256, 256>>>(w);
    k_demod<<<dim3(COUT, NB), 256>>>(y);
    k_wsplit<<<NB * COUT * 9 * 128 / 256, 256>>>(w, y);
    k_conv<<<dim3(NPIX / 128, NB), 256, SMEM_BYTES>>>(x, bias, out);
}

// round 5
// speedup vs baseline: 2.9559x; 1.5046x over previous
#include <cuda_runtime.h>
#include <cuda_fp16.h>
#include <cstdint>

#define CIN   256
#define COUT  256
#define HWD   64
#define NB    32
#define NPIX  4096
#define KTOT  2304            // 9 * 256
#define NSTAGE 72             // K chunks of 32

#define XROW  272             // padded row bytes for x tile [k32][pix128] fp16
#define WROW  80              // padded row bytes for w tile [co][k32] fp16
#define X_SZ  (32 * XROW)     // 8704 per split (hi or lo)
#define XSTAGE (2 * X_SZ)     // 17408 (hi + lo)
#define W_SZ  (256 * WROW)    // 20480
#define OW    (2 * XSTAGE)    // 34816: W region after 2 x-buffers
#define SMEM_BYTES (OW + 3 * W_SZ)   // 96256

// ---------------- device scratch ---------------------------------------------
__device__ float g_wsq[COUT * CIN];
__device__ float g_dmod[NB * COUT];
__device__ __half g_wh[(size_t)NB * COUT * KTOT];   // modulated w fp16, K-major

// ---------------- helpers -----------------------------------------------------
__device__ __forceinline__ uint32_t smem_u32(const void* p) {
    uint32_t a;
    asm("{ .reg .u64 t; cvta.to.shared.u64 t, %1; cvt.u32.u64 %0, t; }" : "=r"(a) : "l"(p));
    return a;
}
__device__ __forceinline__ uint32_t h2u(__half2 v) {
    uint32_t u;
    memcpy(&u, &v, 4);
    return u;
}
__device__ __forceinline__ void cp16(uint32_t dst, const void* src) {
    asm volatile("cp.async.cg.shared.global [%0], [%1], 16;" :: "r"(dst), "l"(src));
}
__device__ __forceinline__ void cp_commit() { asm volatile("cp.async.commit_group;"); }
__device__ __forceinline__ void cp_wait1()  { asm volatile("cp.async.wait_group 1;"); }

__device__ __forceinline__ void ldsm4(uint32_t* r, uint32_t a) {
    asm volatile("ldmatrix.sync.aligned.m8n8.x4.shared.b16 {%0,%1,%2,%3}, [%4];"
                 : "=r"(r[0]), "=r"(r[1]), "=r"(r[2]), "=r"(r[3]) : "r"(a));
}
__device__ __forceinline__ void ldsm4t(uint32_t* r, uint32_t a) {
    asm volatile("ldmatrix.sync.aligned.m8n8.x4.trans.shared.b16 {%0,%1,%2,%3}, [%4];"
                 : "=r"(r[0]), "=r"(r[1]), "=r"(r[2]), "=r"(r[3]) : "r"(a));
}
__device__ __forceinline__ void mma16816(float* c, const uint32_t* a, const uint32_t* b) {
    asm volatile("mma.sync.aligned.m16n8k16.row.col.f32.f16.f16.f32 "
                 "{%0,%1,%2,%3}, {%4,%5,%6,%7}, {%8,%9}, {%0,%1,%2,%3};"
                 : "+f"(c[0]), "+f"(c[1]), "+f"(c[2]), "+f"(c[3])
                 : "r"(a[0]), "r"(a[1]), "r"(a[2]), "r"(a[3]), "r"(b[0]), "r"(b[1]));
}

// ---------------- prologue ----------------------------------------------------
__global__ void k_wsq(const float* __restrict__ w) {
    int idx = blockIdx.x * blockDim.x + threadIdx.x;   // co*256+ci
    const float* p = w + idx * 9;
    float s = 0.f;
#pragma unroll
    for (int k = 0; k < 9; k++) { float v = p[k]; s += v * v; }
    g_wsq[idx] = s;
}

__global__ void k_demod(const float* __restrict__ y) {
    int co = blockIdx.x, b = blockIdx.y, t = threadIdx.x;
    float ym = y[b * CIN + t] + 1.0f;
    float v = g_wsq[co * CIN + t] * ym * ym;
#pragma unroll
    for (int o = 16; o; o >>= 1) v += __shfl_xor_sync(0xffffffffu, v, o);
    __shared__ float sr[8];
    if ((t & 31) == 0) sr[t >> 5] = v;
    __syncthreads();
    if (t == 0) {
        float s = 0.f;
#pragma unroll
        for (int i = 0; i < 8; i++) s += sr[i];
        g_dmod[b * COUT + co] = rsqrtf(s + 1e-8f);
    }
}

// modulate + demodulate + fp16 round; K-major [b][co][kp*256+ci]
__global__ void k_wsplit(const float* __restrict__ w, const float* __restrict__ y) {
    int t = blockIdx.x * 256 + threadIdx.x;
    int cih = t & 127;
    int r   = t >> 7;
    int kp  = r % 9;
    int bc  = r / 9;
    int co = bc & 255, b = bc >> 8;
    int ci = cih * 2;
    float d  = g_dmod[b * COUT + co];
    float y0 = y[b * CIN + ci]     + 1.f;
    float y1 = y[b * CIN + ci + 1] + 1.f;
    float v0 = w[co * KTOT + ci * 9 + kp]       * y0 * d;
    float v1 = w[co * KTOT + (ci + 1) * 9 + kp] * y1 * d;
    __half2 hv = __floats2half2_rn(v0, v1);
    size_t o = ((size_t)(b * COUT + co)) * KTOT + kp * CIN + ci;
    *(__half2*)(g_wh + o) = hv;
}

// ---------------- main conv: HMMA fp16x2 implicit GEMM ------------------------
// CTA: 128 pixels (M) x 256 cout (N), K = 2304. x split fp16 hi/lo, w fp16.
__global__ void __launch_bounds__(256, 1) k_conv(const float* __restrict__ x,
                                                 const float* __restrict__ bias,
                                                 float* __restrict__ out) {
    extern __shared__ char smem[];
    const uint32_t sb0 = smem_u32(smem);
    const int t  = threadIdx.x;
    const int ln = t & 31;
    const int wp = t >> 5;
    const int wm = wp & 1;          // pixel half (64)
    const int wn = wp >> 1;         // cout quarter (64)
    const int b  = blockIdx.y;
    const int n0 = blockIdx.x * 128;

    const float* xb = x + (size_t)b * CIN * NPIX;
    const __half* gwh = g_wh + (size_t)b * COUT * KTOT;

    // ldmatrix lane address components (same layout as validated R3)
    const uint32_t a_lane = (uint32_t)(((ln & 7) + ((ln >> 4) & 1) * 8) * XROW
                                       + (wm * 64 + ((ln >> 3) & 1) * 8) * 2);
    const uint32_t b_lane = (uint32_t)(((ln & 7) + ((ln >> 4) & 1) * 8) * WROW
                                       + ((ln >> 3) & 1) * 16);

    float acc[4][8][4];
#pragma unroll
    for (int i = 0; i < 4; i++)
#pragma unroll
        for (int j = 0; j < 8; j++)
#pragma unroll
            for (int k = 0; k < 4; k++) acc[i][j][k] = 0.f;

    float xv[16];   // 4 ci x 4 consecutive pixels

    // ---- x gather: thread owns pixels 4*ln..4*ln+3 for ci = wp*4..wp*4+3 ----
    auto load_x_regs = [&](int c) {
        const int kp  = c / 8;
        const int cic = (c & 7) * 32;
        const int dr = kp / 3 - 1, dc = kp % 3 - 1;
        const int r2 = (n0 >> 6) + (ln >> 4) + dr;
        const int cb = (ln & 15) * 4 + dc;
        const bool okr = (unsigned)r2 < HWD;
#pragma unroll
        for (int j = 0; j < 16; j++) {
            const int ci = wp * 4 + (j >> 2);
            const int c2 = cb + (j & 3);
            const bool ok = okr && ((unsigned)c2 < HWD);
            xv[j] = ok ? __ldg(xb + (size_t)(cic + ci) * NPIX + r2 * HWD + c2) : 0.f;
        }
    };
    auto store_x = [&](int buf) {
        char* base = smem + buf * XSTAGE;
#pragma unroll
        for (int jc = 0; jc < 4; jc++) {
            const int ci = wp * 4 + jc;
            float v0 = xv[jc * 4], v1 = xv[jc * 4 + 1], v2 = xv[jc * 4 + 2], v3 = xv[jc * 4 + 3];
            __half2 h01 = __floats2half2_rn(v0, v1);
            __half2 h23 = __floats2half2_rn(v2, v3);
            __half2 l01 = __floats2half2_rn(v0 - __half2float(__low2half(h01)),
                                            v1 - __half2float(__high2half(h01)));
            __half2 l23 = __floats2half2_rn(v2 - __half2float(__low2half(h23)),
                                            v3 - __half2float(__high2half(h23)));
            const uint32_t off = (uint32_t)(ci * XROW + ln * 8);
            *(uint2*)(base + off)        = make_uint2(h2u(h01), h2u(h23));
            *(uint2*)(base + X_SZ + off) = make_uint2(h2u(l01), h2u(l23));
        }
    };
    auto load_w = [&](int c) {
        const int kp  = c / 8;
        const int cic = (c & 7) * 32;
        const int wbuf = c % 3;
        const __half* src = gwh + (size_t)t * KTOT + kp * 256 + cic;
        const uint32_t dst = sb0 + OW + wbuf * W_SZ + t * WROW;
#pragma unroll
        for (int q = 0; q < 4; q++) cp16(dst + q * 16, src + q * 8);
    };

    // ---- prime ----
    load_w(0); cp_commit();
    load_w(1); cp_commit();
    load_x_regs(0);
    store_x(0);
    cp_wait1();                 // W(0) ready
    __syncthreads();

#pragma unroll 1
    for (int c = 0; c < NSTAGE; c++) {
        const int xbuf = c & 1;
        const uint32_t xs = sb0 + xbuf * XSTAGE;
        const uint32_t ws = sb0 + OW + (c % 3) * W_SZ;
        const bool more = (c + 1 < NSTAGE);
        if (c + 2 < NSTAGE) load_w(c + 2);
        cp_commit();
        if (more) load_x_regs(c + 1);

        // ---- compute stage c ----
#pragma unroll
        for (int s = 0; s < 2; s++) {
            uint32_t Ah[16], Al[16];
            const uint32_t ax = xs + a_lane + s * 16 * XROW;
#pragma unroll
            for (int mt = 0; mt < 4; mt++) ldsm4t(Ah + mt * 4, ax + mt * 32);
#pragma unroll
            for (int mt = 0; mt < 4; mt++) ldsm4t(Al + mt * 4, ax + X_SZ + mt * 32);
#pragma unroll
            for (int h = 0; h < 2; h++) {
                uint32_t Bh[8];
                const uint32_t bw = ws + b_lane + (wn * 64 + h * 32) * WROW + s * 32;
                ldsm4(Bh,     bw);
                ldsm4(Bh + 4, bw + 16 * WROW);
#pragma unroll
                for (int mt = 0; mt < 4; mt++)
#pragma unroll
                    for (int q = 0; q < 4; q++)
                        mma16816(acc[mt][h * 4 + q], Ah + mt * 4, Bh + q * 2);
#pragma unroll
                for (int mt = 0; mt < 4; mt++)
#pragma unroll
                    for (int q = 0; q < 4; q++)
                        mma16816(acc[mt][h * 4 + q], Al + mt * 4, Bh + q * 2);
            }
        }

        if (more) store_x(xbuf ^ 1);
        cp_wait1();             // W(c+1) ready; W(c+2) may still fly
        __syncthreads();
    }

    // ---- epilogue ----
#pragma unroll
    for (int h = 0; h < 2; h++)
#pragma unroll
        for (int q = 0; q < 4; q++) {
            const int co0 = wn * 64 + h * 32 + (q >> 1) * 16 + (q & 1) * 8 + (ln & 3) * 2;
            const float b0 = __ldg(&bias[co0]);
            const float b1 = __ldg(&bias[co0 + 1]);
#pragma unroll
            for (int mt = 0; mt < 4; mt++) {
                const int pix = n0 + wm * 64 + mt * 16 + (ln >> 2);
                float* o = out + ((size_t)b * COUT + co0) * NPIX + pix;
                const float* C = acc[mt][h * 4 + q];
                o[0]        = C[0] + b0;
                o[NPIX]     = C[1] + b1;
                o[8]        = C[2] + b0;
                o[NPIX + 8] = C[3] + b1;
            }
        }
}

// ---------------- launch ------------------------------------------------------
extern "C" void kernel_launch(void* const* d_in, const int* in_sizes, int n_in,
                              void* d_out, int out_size) {
    const float* x    = (const float*)d_in[0];
    const float* y    = (const float*)d_in[1];
    const float* w    = (const float*)d_in[2];
    const float* bias = (const float*)d_in[3];
    float* out        = (float*)d_out;

    cudaFuncSetAttribute(k_conv, cudaFuncAttributeMaxDynamicSharedMemorySize, SMEM_BYTES);

    k_wsq<<<COUT * CIN / 256, 256>>>(w);
    k_demod<<<dim3(COUT, NB), 256>>>(y);
    k_wsplit<<<NB * COUT * 9 * 128 / 256, 256>>>(w, y);
    k_conv<<<dim3(NPIX / 128, NB), 256, SMEM_BYTES>>>(x, bias, out);
}

// round 6
// speedup vs baseline: 4.1832x; 1.4152x over previous
#include <cuda_runtime.h>
#include <cuda_fp16.h>
#include <cstdint>

#define CIN   256
#define COUT  256
#define HWD   64
#define NB    32
#define NPIX  4096
#define KTOT  2304            // 9 * 256
#define NSTAGE 72             // K chunks of 32

#define XROW  272             // padded row bytes for x tile [k32][pix128] fp16
#define WROW  80              // padded row bytes for w tile [co][k32] fp16
#define X_SZ  (32 * XROW)     // 8704
#define W_SZ  (256 * WROW)    // 20480
#define ST_SZ (X_SZ + W_SZ)   // 29184
#define NRING 4
#define SMEM_BYTES (NRING * ST_SZ)   // 116736

// ---------------- device scratch ---------------------------------------------
__device__ float g_wsq[COUT * CIN];
__device__ float g_dmod[NB * COUT];
__device__ __half g_wh[(size_t)NB * COUT * KTOT];          // modulated w fp16, K-major
__device__ __half g_xh[(size_t)3 * NB * CIN * NPIX];       // x fp16, 3 dc-shifted copies

// ---------------- helpers -----------------------------------------------------
__device__ __forceinline__ uint32_t smem_u32(const void* p) {
    uint32_t a;
    asm("{ .reg .u64 t; cvta.to.shared.u64 t, %1; cvt.u32.u64 %0, t; }" : "=r"(a) : "l"(p));
    return a;
}
__device__ __forceinline__ void cp16(uint32_t dst, const void* src) {
    asm volatile("cp.async.cg.shared.global [%0], [%1], 16;" :: "r"(dst), "l"(src));
}
__device__ __forceinline__ void cp16z(uint32_t dst, const void* src, uint32_t nbytes) {
    asm volatile("cp.async.cg.shared.global [%0], [%1], 16, %2;"
                 :: "r"(dst), "l"(src), "r"(nbytes));
}
__device__ __forceinline__ void cp_commit() { asm volatile("cp.async.commit_group;"); }
__device__ __forceinline__ void cp_wait2()  { asm volatile("cp.async.wait_group 2;"); }

__device__ __forceinline__ void ldsm4(uint32_t* r, uint32_t a) {
    asm volatile("ldmatrix.sync.aligned.m8n8.x4.shared.b16 {%0,%1,%2,%3}, [%4];"
                 : "=r"(r[0]), "=r"(r[1]), "=r"(r[2]), "=r"(r[3]) : "r"(a));
}
__device__ __forceinline__ void ldsm4t(uint32_t* r, uint32_t a) {
    asm volatile("ldmatrix.sync.aligned.m8n8.x4.trans.shared.b16 {%0,%1,%2,%3}, [%4];"
                 : "=r"(r[0]), "=r"(r[1]), "=r"(r[2]), "=r"(r[3]) : "r"(a));
}
__device__ __forceinline__ void mma16816(float* c, const uint32_t* a, const uint32_t* b) {
    asm volatile("mma.sync.aligned.m16n8k16.row.col.f32.f16.f16.f32 "
                 "{%0,%1,%2,%3}, {%4,%5,%6,%7}, {%8,%9}, {%0,%1,%2,%3};"
                 : "+f"(c[0]), "+f"(c[1]), "+f"(c[2]), "+f"(c[3])
                 : "r"(a[0]), "r"(a[1]), "r"(a[2]), "r"(a[3]), "r"(b[0]), "r"(b[1]));
}

// ---------------- prologue ----------------------------------------------------
__global__ void k_wsq(const float* __restrict__ w) {
    int idx = blockIdx.x * blockDim.x + threadIdx.x;   // co*256+ci
    const float* p = w + idx * 9;
    float s = 0.f;
#pragma unroll
    for (int k = 0; k < 9; k++) { float v = p[k]; s += v * v; }
    g_wsq[idx] = s;
}

__global__ void k_demod(const float* __restrict__ y) {
    int co = blockIdx.x, b = blockIdx.y, t = threadIdx.x;
    float ym = y[b * CIN + t] + 1.0f;
    float v = g_wsq[co * CIN + t] * ym * ym;
#pragma unroll
    for (int o = 16; o; o >>= 1) v += __shfl_xor_sync(0xffffffffu, v, o);
    __shared__ float sr[8];
    if ((t & 31) == 0) sr[t >> 5] = v;
    __syncthreads();
    if (t == 0) {
        float s = 0.f;
#pragma unroll
        for (int i = 0; i < 8; i++) s += sr[i];
        g_dmod[b * COUT + co] = rsqrtf(s + 1e-8f);
    }
}

// modulate + demodulate + fp16 round; K-major [b][co][kp*256+ci]
__global__ void k_wsplit(const float* __restrict__ w, const float* __restrict__ y) {
    int t = blockIdx.x * 256 + threadIdx.x;
    int cih = t & 127;
    int r   = t >> 7;
    int kp  = r % 9;
    int bc  = r / 9;
    int co = bc & 255, b = bc >> 8;
    int ci = cih * 2;
    float d  = g_dmod[b * COUT + co];
    float y0 = y[b * CIN + ci]     + 1.f;
    float y1 = y[b * CIN + ci + 1] + 1.f;
    float v0 = w[co * KTOT + ci * 9 + kp]       * y0 * d;
    float v1 = w[co * KTOT + (ci + 1) * 9 + kp] * y1 * d;
    __half2 hv = __floats2half2_rn(v0, v1);
    size_t o = ((size_t)(b * COUT + co)) * KTOT + kp * CIN + ci;
    *(__half2*)(g_wh + o) = hv;
}

// x fp32 -> fp16, 3 column-shifted zero-padded copies. Thread: 4 pixels.
__global__ void k_xcvt(const float* __restrict__ x) {
    int idx = blockIdx.x * 256 + threadIdx.x;          // NB*CIN*1024 threads
    int plane = idx >> 10;                             // b*CIN + ci
    int p0    = (idx & 1023) * 4;
    int c0    = p0 & 63;
    const float* xp = x + (size_t)plane * NPIX + p0;
    float4 v = *(const float4*)xp;
    float xm  = (c0 > 0)  ? xp[-1] : 0.f;
    float xp4 = (c0 < 60) ? xp[4]  : 0.f;
    __half2 o[3][2];
    o[0][0] = __floats2half2_rn(xm,  v.x);  o[0][1] = __floats2half2_rn(v.y, v.z);
    o[1][0] = __floats2half2_rn(v.x, v.y);  o[1][1] = __floats2half2_rn(v.z, v.w);
    o[2][0] = __floats2half2_rn(v.y, v.z);  o[2][1] = __floats2half2_rn(v.w, xp4);
#pragma unroll
    for (int d = 0; d < 3; d++) {
        __half* dst = g_xh + ((size_t)d * NB * CIN + plane) * NPIX + p0;
        *(__half2*)dst       = o[d][0];
        *(__half2*)(dst + 2) = o[d][1];
    }
}

// ---------------- main conv: HMMA fp16 single-pass implicit GEMM --------------
// CTA: 128 pixels (M) x 256 cout (N), K = 2304, 4-deep cp.async ring.
__global__ void __launch_bounds__(256, 1) k_conv(const float* __restrict__ bias,
                                                 float* __restrict__ out) {
    extern __shared__ char smem[];
    const uint32_t sb0 = smem_u32(smem);
    const int t  = threadIdx.x;
    const int ln = t & 31;
    const int wp = t >> 5;
    const int wm = wp & 1;          // pixel half (64)
    const int wn = wp >> 1;         // cout quarter (64)
    const int b  = blockIdx.y;
    const int n0 = blockIdx.x * 128;
    const int r0 = blockIdx.x * 2;  // first image row of this tile

    const __half* gwh = g_wh + (size_t)b * COUT * KTOT;

    const uint32_t a_lane = (uint32_t)(((ln & 7) + ((ln >> 4) & 1) * 8) * XROW
                                       + (wm * 64 + ((ln >> 3) & 1) * 8) * 2);
    const uint32_t b_lane = (uint32_t)(((ln & 7) + ((ln >> 4) & 1) * 8) * WROW
                                       + ((ln >> 3) & 1) * 16);

    float acc[4][8][4];
#pragma unroll
    for (int i = 0; i < 4; i++)
#pragma unroll
        for (int j = 0; j < 8; j++)
#pragma unroll
            for (int k = 0; k < 4; k++) acc[i][j][k] = 0.f;

    // ---- stage loader: X tile (2 chunks/thread) + W tile (4 chunks/thread) ---
    auto load_stage = [&](int cs) {
        const int kp  = cs >> 3;                 // 0..8
        const int cic = (cs & 7) * 32;
        const int dr  = kp / 3 - 1;
        const int dv  = kp % 3;                  // dc + 1
        const uint32_t sbase = sb0 + (cs & 3) * ST_SZ;
        const __half* xplane = g_xh + ((size_t)dv * NB + b) * CIN * NPIX;
#pragma unroll
        for (int j = 0; j < 2; j++) {
            const int chunk = t * 2 + j;         // 0..511
            const int ci  = chunk >> 4;
            const int ch  = chunk & 15;
            const int gr  = r0 + (ch >> 3) + dr;
            const bool ok = (unsigned)gr < HWD;
            const __half* src = xplane + (size_t)(cic + ci) * NPIX
                                + (ok ? gr : 0) * HWD + (ch & 7) * 8;
            cp16z(sbase + ci * XROW + ch * 16, src, ok ? 16u : 0u);
        }
        const __half* wsrc = gwh + (size_t)t * KTOT + kp * 256 + cic;
        const uint32_t wdst = sbase + X_SZ + t * WROW;
#pragma unroll
        for (int q = 0; q < 4; q++) cp16(wdst + q * 16, wsrc + q * 8);
    };

    // ---- prime 3 stages ----
    load_stage(0); cp_commit();
    load_stage(1); cp_commit();
    load_stage(2); cp_commit();
    cp_wait2();
    __syncthreads();

#pragma unroll 1
    for (int c = 0; c < NSTAGE; c++) {
        const uint32_t xs = sb0 + (c & 3) * ST_SZ;
        const uint32_t ws = xs + X_SZ;
        if (c + 3 < NSTAGE) load_stage(c + 3);
        cp_commit();

#pragma unroll
        for (int s = 0; s < 2; s++) {
            uint32_t Ah[16];
            const uint32_t ax = xs + a_lane + s * 16 * XROW;
#pragma unroll
            for (int mt = 0; mt < 4; mt++) ldsm4t(Ah + mt * 4, ax + mt * 32);
#pragma unroll
            for (int h = 0; h < 2; h++) {
                uint32_t Bh[8];
                const uint32_t bw = ws + b_lane + (wn * 64 + h * 32) * WROW + s * 32;
                ldsm4(Bh,     bw);
                ldsm4(Bh + 4, bw + 16 * WROW);
#pragma unroll
                for (int mt = 0; mt < 4; mt++)
#pragma unroll
                    for (int q = 0; q < 4; q++)
                        mma16816(acc[mt][h * 4 + q], Ah + mt * 4, Bh + q * 2);
            }
        }

        cp_wait2();
        __syncthreads();
    }

    // ---- epilogue ----
#pragma unroll
    for (int h = 0; h < 2; h++)
#pragma unroll
        for (int q = 0; q < 4; q++) {
            const int co0 = wn * 64 + h * 32 + (q >> 1) * 16 + (q & 1) * 8 + (ln & 3) * 2;
            const float b0 = __ldg(&bias[co0]);
            const float b1 = __ldg(&bias[co0 + 1]);
#pragma unroll
            for (int mt = 0; mt < 4; mt++) {
                const int pix = n0 + wm * 64 + mt * 16 + (ln >> 2);
                float* o = out + ((size_t)b * COUT + co0) * NPIX + pix;
                const float* C = acc[mt][h * 4 + q];
                o[0]        = C[0] + b0;
                o[NPIX]     = C[1] + b1;
                o[8]        = C[2] + b0;
                o[NPIX + 8] = C[3] + b1;
            }
        }
}

// ---------------- launch ------------------------------------------------------
extern "C" void kernel_launch(void* const* d_in, const int* in_sizes, int n_in,
                              void* d_out, int out_size) {
    const float* x    = (const float*)d_in[0];
    const float* y    = (const float*)d_in[1];
    const float* w    = (const float*)d_in[2];
    const float* bias = (const float*)d_in[3];
    float* out        = (float*)d_out;

    cudaFuncSetAttribute(k_conv, cudaFuncAttributeMaxDynamicSharedMemorySize, SMEM_BYTES);

    k_wsq<<<COUT * CIN / 256, 256>>>(w);
    k_demod<<<dim3(COUT, NB), 256>>>(y);
    k_wsplit<<<NB * COUT * 9 * 128 / 256, 256>>>(w, y);
    k_xcvt<<<NB * CIN * 1024 / 256, 256>>>(x);
    k_conv<<<dim3(NPIX / 128, NB), 256, SMEM_BYTES>>>(bias, out);
}

// round 7
// speedup vs baseline: 7.8121x; 1.8675x over previous
#include <cuda_runtime.h>
#include <cuda_fp16.h>
#include <cstdint>

#define CIN   256
#define COUT  256
#define HWD   64
#define NB    32
#define NPIX  4096
#define KTOT  2304            // 9 * 256
#define NSTAGE 36             // K chunks of 64

#define XROW  272             // padded row bytes for x tile [k64][pix128] fp16
#define WROW  144             // padded row bytes for w tile [co][k64] fp16
#define X_SZ  (64 * XROW)     // 17408
#define W_SZ  (256 * WROW)    // 36864
#define ST_SZ (X_SZ + W_SZ)   // 54272
#define NRING 3
#define SMEM_BYTES (NRING * ST_SZ)   // 162816

// ---------------- device scratch ---------------------------------------------
__device__ float g_wsq[COUT * CIN];
__device__ float g_dmod[NB * COUT];
__device__ float g_wt[(size_t)COUT * KTOT];                // w fp32, K-major per co
__device__ __half g_wh[(size_t)NB * COUT * KTOT];          // modulated w fp16, K-major
__device__ __half g_xh[(size_t)3 * NB * CIN * NPIX];       // x fp16, 3 dc-shifted copies

// ---------------- helpers -----------------------------------------------------
__device__ __forceinline__ uint32_t smem_u32(const void* p) {
    uint32_t a;
    asm("{ .reg .u64 t; cvta.to.shared.u64 t, %1; cvt.u32.u64 %0, t; }" : "=r"(a) : "l"(p));
    return a;
}
__device__ __forceinline__ void cp16(uint32_t dst, const void* src) {
    asm volatile("cp.async.cg.shared.global [%0], [%1], 16;" :: "r"(dst), "l"(src));
}
__device__ __forceinline__ void cp16z(uint32_t dst, const void* src, uint32_t nbytes) {
    asm volatile("cp.async.cg.shared.global [%0], [%1], 16, %2;"
                 :: "r"(dst), "l"(src), "r"(nbytes));
}
__device__ __forceinline__ void cp_commit() { asm volatile("cp.async.commit_group;"); }
__device__ __forceinline__ void cp_wait1()  { asm volatile("cp.async.wait_group 1;"); }

__device__ __forceinline__ void ldsm4(uint32_t* r, uint32_t a) {
    asm volatile("ldmatrix.sync.aligned.m8n8.x4.shared.b16 {%0,%1,%2,%3}, [%4];"
                 : "=r"(r[0]), "=r"(r[1]), "=r"(r[2]), "=r"(r[3]) : "r"(a));
}
__device__ __forceinline__ void ldsm4t(uint32_t* r, uint32_t a) {
    asm volatile("ldmatrix.sync.aligned.m8n8.x4.trans.shared.b16 {%0,%1,%2,%3}, [%4];"
                 : "=r"(r[0]), "=r"(r[1]), "=r"(r[2]), "=r"(r[3]) : "r"(a));
}
__device__ __forceinline__ void mma16816(float* c, const uint32_t* a, const uint32_t* b) {
    asm volatile("mma.sync.aligned.m16n8k16.row.col.f32.f16.f16.f32 "
                 "{%0,%1,%2,%3}, {%4,%5,%6,%7}, {%8,%9}, {%0,%1,%2,%3};"
                 : "+f"(c[0]), "+f"(c[1]), "+f"(c[2]), "+f"(c[3])
                 : "r"(a[0]), "r"(a[1]), "r"(a[2]), "r"(a[3]), "r"(b[0]), "r"(b[1]));
}

// ---------------- prologue ----------------------------------------------------
__global__ void k_wsq(const float* __restrict__ w) {
    int idx = blockIdx.x * blockDim.x + threadIdx.x;   // co*256+ci
    const float* p = w + idx * 9;
    float s = 0.f;
#pragma unroll
    for (int k = 0; k < 9; k++) { float v = p[k]; s += v * v; }
    g_wsq[idx] = s;
}

__global__ void k_demod(const float* __restrict__ y) {
    int co = blockIdx.x, b = blockIdx.y, t = threadIdx.x;
    float ym = y[b * CIN + t] + 1.0f;
    float v = g_wsq[co * CIN + t] * ym * ym;
#pragma unroll
    for (int o = 16; o; o >>= 1) v += __shfl_xor_sync(0xffffffffu, v, o);
    __shared__ float sr[8];
    if ((t & 31) == 0) sr[t >> 5] = v;
    __syncthreads();
    if (t == 0) {
        float s = 0.f;
#pragma unroll
        for (int i = 0; i < 8; i++) s += sr[i];
        g_dmod[b * COUT + co] = rsqrtf(s + 1e-8f);
    }
}

// w [co][ci][kp] -> g_wt [co][kp*256+ci]  (coalesced writes)
__global__ void k_wt(const float* __restrict__ w) {
    int idx = blockIdx.x * 256 + threadIdx.x;   // 589824
    int ci = idx & 255;
    int r  = idx >> 8;          // 0..2303
    int kp = r % 9;
    int co = r / 9;
    g_wt[(size_t)co * KTOT + kp * 256 + ci] = w[(size_t)co * KTOT + ci * 9 + kp];
}

// modulate + demodulate + fp16 round; fully coalesced both sides
__global__ void k_wsplit(const float* __restrict__ y) {
    int t = blockIdx.x * 256 + threadIdx.x;    // NB*COUT*KTOT/2 threads
    int h  = t & 127;
    int r  = t >> 7;            // (b, co, kp)
    int kp = r % 9;
    int bc = r / 9;
    int co = bc & 255, b = bc >> 8;
    int ci = h * 2;
    float d = g_dmod[b * COUT + co];
    float2 yv = *(const float2*)&y[b * CIN + ci];
    float2 wv = *(const float2*)&g_wt[(size_t)co * KTOT + kp * 256 + ci];
    float v0 = wv.x * (yv.x + 1.f) * d;
    float v1 = wv.y * (yv.y + 1.f) * d;
    size_t o = ((size_t)(b * COUT + co)) * KTOT + kp * 256 + ci;
    *(__half2*)(g_wh + o) = __floats2half2_rn(v0, v1);
}

// x fp32 -> fp16, 3 column-shifted zero-padded copies. Thread: 4 pixels.
__global__ void k_xcvt(const float* __restrict__ x) {
    int idx = blockIdx.x * 256 + threadIdx.x;          // NB*CIN*1024 threads
    int plane = idx >> 10;                             // b*CIN + ci
    int p0    = (idx & 1023) * 4;
    int c0    = p0 & 63;
    const float* xp = x + (size_t)plane * NPIX + p0;
    float4 v = *(const float4*)xp;
    float xm  = (c0 > 0)  ? xp[-1] : 0.f;
    float xp4 = (c0 < 60) ? xp[4]  : 0.f;
    __half2 o[3][2];
    o[0][0] = __floats2half2_rn(xm,  v.x);  o[0][1] = __floats2half2_rn(v.y, v.z);
    o[1][0] = __floats2half2_rn(v.x, v.y);  o[1][1] = __floats2half2_rn(v.z, v.w);
    o[2][0] = __floats2half2_rn(v.y, v.z);  o[2][1] = __floats2half2_rn(v.w, xp4);
#pragma unroll
    for (int d = 0; d < 3; d++) {
        __half* dst = g_xh + ((size_t)d * NB * CIN + plane) * NPIX + p0;
        *(__half2*)dst       = o[d][0];
        *(__half2*)(dst + 2) = o[d][1];
    }
}

// ---------------- main conv: HMMA fp16 implicit GEMM, K64 stages --------------
// CTA: 128 pixels (M) x 256 cout (N), K = 2304, ring-3 cp.async, frag dbl-buf.
__global__ void __launch_bounds__(256, 1) k_conv(const float* __restrict__ bias,
                                                 float* __restrict__ out) {
    extern __shared__ char smem[];
    const uint32_t sb0 = smem_u32(smem);
    const int t  = threadIdx.x;
    const int ln = t & 31;
    const int wp = t >> 5;
    const int wm = wp & 1;          // pixel half (64)
    const int wn = wp >> 1;         // cout quarter (64)
    const int b  = blockIdx.y;
    const int n0 = blockIdx.x * 128;
    const int r0 = blockIdx.x * 2;  // first image row of this tile

    const __half* gwh = g_wh + (size_t)b * COUT * KTOT;

    const uint32_t a_lane = (uint32_t)(((ln & 7) + ((ln >> 4) & 1) * 8) * XROW
                                       + (wm * 64 + ((ln >> 3) & 1) * 8) * 2);
    const uint32_t b_lane = (uint32_t)(((ln & 7) + ((ln >> 4) & 1) * 8) * WROW
                                       + ((ln >> 3) & 1) * 16);

    float acc[4][8][4];
#pragma unroll
    for (int i = 0; i < 4; i++)
#pragma unroll
        for (int j = 0; j < 8; j++)
#pragma unroll
            for (int k = 0; k < 4; k++) acc[i][j][k] = 0.f;

    uint32_t Af[2][16], Bf[2][16];

    // ---- stage loader: X (4 chunks/thread) + W (8 chunks/thread) -------------
    auto load_stage = [&](int cs) {
        const int kp  = cs >> 2;                 // 0..8
        const int cic = (cs & 3) * 64;
        const int dr  = kp / 3 - 1;
        const int dv  = kp % 3;                  // dc + 1
        const uint32_t sbase = sb0 + (cs % NRING) * ST_SZ;
        const __half* xplane = g_xh + ((size_t)dv * NB + b) * CIN * NPIX;
#pragma unroll
        for (int j = 0; j < 4; j++) {
            const int chunk = j * 256 + t;       // 0..1023
            const int ci  = chunk >> 4;
            const int ch  = chunk & 15;
            const int gr  = r0 + (ch >> 3) + dr;
            const bool ok = (unsigned)gr < HWD;
            const __half* src = xplane + (size_t)(cic + ci) * NPIX
                                + (ok ? gr : 0) * HWD + (ch & 7) * 8;
            cp16z(sbase + ci * XROW + ch * 16, src, ok ? 16u : 0u);
        }
        const __half* wbase = gwh + kp * 256 + cic;
        const uint32_t wdst = sbase + X_SZ;
#pragma unroll
        for (int q = 0; q < 8; q++) {
            const int chunk = q * 256 + t;       // 0..2047
            const int row = chunk >> 3;
            const int u   = chunk & 7;
            cp16(wdst + row * WROW + u * 16, wbase + (size_t)row * KTOT + u * 8);
        }
    };

    // ---- frag loader for k16 slice sl of the stage at (xs, ws) ---------------
    auto load_frags = [&](uint32_t xs, uint32_t ws, int sl, int pb) {
        const uint32_t ax = xs + a_lane + sl * 16 * XROW;
#pragma unroll
        for (int mt = 0; mt < 4; mt++) ldsm4t(&Af[pb][mt * 4], ax + mt * 32);
        const uint32_t bw = ws + b_lane + wn * 64 * WROW + sl * 32;
        ldsm4(&Bf[pb][0],  bw);
        ldsm4(&Bf[pb][4],  bw + 16 * WROW);
        ldsm4(&Bf[pb][8],  bw + 32 * WROW);
        ldsm4(&Bf[pb][12], bw + 48 * WROW);
    };
    auto compute = [&](int pb) {
#pragma unroll
        for (int h = 0; h < 2; h++)
#pragma unroll
            for (int mt = 0; mt < 4; mt++)
#pragma unroll
                for (int q = 0; q < 4; q++)
                    mma16816(acc[mt][h * 4 + q], &Af[pb][mt * 4], &Bf[pb][h * 8 + q * 2]);
    };

    // ---- prime ----
    load_stage(0); cp_commit();
    load_stage(1); cp_commit();
    cp_wait1();
    __syncthreads();
    load_frags(sb0, sb0 + X_SZ, 0, 0);

#pragma unroll 1
    for (int c = 0; c < NSTAGE; c++) {
        const uint32_t xs = sb0 + (c % NRING) * ST_SZ;
        const uint32_t ws = xs + X_SZ;
        if (c + 2 < NSTAGE) load_stage(c + 2);
        cp_commit();

#pragma unroll
        for (int sl = 0; sl < 4; sl++) {
            const int pb = sl & 1;
            if (sl < 3) load_frags(xs, ws, sl + 1, pb ^ 1);
            compute(pb);
        }

        cp_wait1();
        __syncthreads();
        if (c + 1 < NSTAGE) {
            const uint32_t nxs = sb0 + ((c + 1) % NRING) * ST_SZ;
            load_frags(nxs, nxs + X_SZ, 0, 0);
        }
    }

    // ---- epilogue ----
#pragma unroll
    for (int h = 0; h < 2; h++)
#pragma unroll
        for (int q = 0; q < 4; q++) {
            const int co0 = wn * 64 + h * 32 + (q >> 1) * 16 + (q & 1) * 8 + (ln & 3) * 2;
            const float b0 = __ldg(&bias[co0]);
            const float b1 = __ldg(&bias[co0 + 1]);
#pragma unroll
            for (int mt = 0; mt < 4; mt++) {
                const int pix = n0 + wm * 64 + mt * 16 + (ln >> 2);
                float* o = out + ((size_t)b * COUT + co0) * NPIX + pix;
                const float* C = acc[mt][h * 4 + q];
                o[0]        = C[0] + b0;
                o[NPIX]     = C[1] + b1;
                o[8]        = C[2] + b0;
                o[NPIX + 8] = C[3] + b1;
            }
        }
}

// ---------------- launch ------------------------------------------------------
extern "C" void kernel_launch(void* const* d_in, const int* in_sizes, int n_in,
                              void* d_out, int out_size) {
    const float* x    = (const float*)d_in[0];
    const float* y    = (const float*)d_in[1];
    const float* w    = (const float*)d_in[2];
    const float* bias = (const float*)d_in[3];
    float* out        = (float*)d_out;

    cudaFuncSetAttribute(k_conv, cudaFuncAttributeMaxDynamicSharedMemorySize, SMEM_BYTES);

    k_wsq<<<COUT * CIN / 256, 256>>>(w);
    k_demod<<<dim3(COUT, NB), 256>>>(y);
    k_wt<<<KTOT, 256>>>(w);
    k_wsplit<<<NB * COUT * KTOT / 2 / 256, 256>>>(y);
    k_xcvt<<<NB * CIN * 1024 / 256, 256>>>(x);
    k_conv<<<dim3(NPIX / 128, NB), 256, SMEM_BYTES>>>(bias, out);
}